// round 13
// baseline (speedup 1.0000x reference)
#include <cuda_runtime.h>
#include <stdint.h>

#define DATA_DIM  4096
#define PAIRS     (DATA_DIM / 2)     // 2048
#define QUADS     (DATA_DIM / 4)     // 1024 float4 per row
#define ROW_BYTES (DATA_DIM * 4)     // 16384
#define BATCH     16384
#define NBLK      (148 * 3)          // persistent CTAs, 3/SM (64KB smem each)
#define TPB       256
#define MODM      ((unsigned long long)(BATCH + NBLK))

// Dynamic smem layout
#define SM_IN0   0
#define SM_IN1   16384
#define SM_OUT0  32768
#define SM_OUT1  49152
#define SM_MBAR  65536               // two 8-byte mbarriers
#define SMEM_SZ  (65536 + 64)

// Work-stealing counter. Zero at module load; each launch consumes exactly
// BATCH real grabs + NBLK terminator grabs (each CTA stops grabbing at its
// first terminator), so the counter advances by exactly MODM per launch and
// row = v % MODM stays valid across graph replays with no reset.
__device__ unsigned long long g_ctr;

__device__ __forceinline__ int grab_row() {
    return (int)(atomicAdd(&g_ctr, 1ULL) % MODM);
}

__device__ __forceinline__ void mbar_init(uint32_t mbar, uint32_t cnt) {
    asm volatile("mbarrier.init.shared.b64 [%0], %1;" :: "r"(mbar), "r"(cnt) : "memory");
}
__device__ __forceinline__ void mbar_expect_tx(uint32_t mbar, uint32_t bytes) {
    asm volatile("mbarrier.arrive.expect_tx.shared.b64 _, [%0], %1;"
                 :: "r"(mbar), "r"(bytes) : "memory");
}
__device__ __forceinline__ void mbar_wait(uint32_t mbar, uint32_t parity) {
    uint32_t done;
    asm volatile(
        "{\n\t.reg .pred p;\n\t"
        "mbarrier.try_wait.parity.acquire.cta.shared::cta.b64 p, [%1], %2;\n\t"
        "selp.b32 %0, 1, 0, p;\n\t}"
        : "=r"(done) : "r"(mbar), "r"(parity) : "memory");
    if (!done) {
        asm volatile(
            "{\n\t.reg .pred P1;\n\t"
            "W_%=:\n\t"
            "mbarrier.try_wait.parity.acquire.cta.shared::cta.b64 P1, [%0], %1, 0x989680;\n\t"
            "@P1 bra.uni D_%=;\n\t"
            "bra.uni W_%=;\n\t"
            "D_%=:\n\t}"
            :: "r"(mbar), "r"(parity) : "memory");
    }
}
// Streaming (no-reuse) L2 policy: evict_first on both directions.
__device__ __forceinline__ uint64_t mk_policy() {
    uint64_t pol;
    asm volatile("createpolicy.fractional.L2::evict_first.b64 %0, 1.0;" : "=l"(pol));
    return pol;
}
__device__ __forceinline__ void bulk_load_row(uint32_t sdst, const void* gsrc,
                                              uint32_t mbar, uint64_t pol) {
    asm volatile(
        "cp.async.bulk.shared::cta.global.mbarrier::complete_tx::bytes.L2::cache_hint"
        " [%0], [%1], %2, [%3], %4;"
        :: "r"(sdst), "l"(gsrc), "r"((uint32_t)ROW_BYTES), "r"(mbar), "l"(pol)
        : "memory");
}
__device__ __forceinline__ void bulk_store_row(void* gdst, uint32_t ssrc, uint64_t pol) {
    asm volatile("cp.async.bulk.global.shared::cta.bulk_group.L2::cache_hint"
                 " [%0], [%1], %2, %3;"
                 :: "l"(gdst), "r"(ssrc), "r"((uint32_t)ROW_BYTES), "l"(pol) : "memory");
    asm volatile("cp.async.bulk.commit_group;" ::: "memory");
}
// Free the older out-buffer as soon as TMA has finished READING it from smem
// (do not wait for the DRAM write to complete).
__device__ __forceinline__ void bulk_store_wait_read1() {
    asm volatile("cp.async.bulk.wait_group.read 1;" ::: "memory");
}
__device__ __forceinline__ void bulk_store_wait0() {
    asm volatile("cp.async.bulk.wait_group 0;" ::: "memory");
}
__device__ __forceinline__ void fence_async() {
    asm volatile("fence.proxy.async.shared::cta;" ::: "memory");
}

// Persistent CTAs. Per row: one TMA bulk load in, CTA-wide smem gather
// (2x LDS.64 -> STS.128, conflict-free stores), one TMA bulk store out.
// Double-buffered input AND output staging; atomic work stealing.
__global__ void __launch_bounds__(TPB)
permute_tma_kernel(const float* __restrict__ z, const void* __restrict__ perm,
                   float* __restrict__ out) {
    extern __shared__ char smem[];
    __shared__ int s_next;

    const int tid = threadIdx.x;
    const uint32_t sbase = (uint32_t)__cvta_generic_to_shared(smem);
    const uint32_t mbar[2] = { sbase + SM_MBAR, sbase + SM_MBAR + 8 };
    float2* const inb[2]  = { (float2*)(smem + SM_IN0),  (float2*)(smem + SM_IN1) };
    float4* const outb[2] = { (float4*)(smem + SM_OUT0), (float4*)(smem + SM_OUT1) };
    const uint64_t pol = mk_policy();

    // ---- Pair-map -> registers. Quad i needs source pairs perm[4i]>>1 and
    // perm[4i+2]>>1. dtype detect: perm[1] is always odd => int32 word[1]!=0;
    // little-endian int64 high word of perm[0] == 0.
    const int* p32 = (const int*)perm;
    const bool is64 = (p32[1] == 0) && (p32[3] == 0) && (p32[5] == 0) && (p32[7] == 0);
    int2 pq[4];
    #pragma unroll
    for (int k = 0; k < 4; k++) {
        int i = tid + k * TPB;
        int e0, e1;
        if (is64) {
            e0 = (int)((const long long*)perm)[4 * i];
            e1 = (int)((const long long*)perm)[4 * i + 2];
        } else {
            e0 = p32[4 * i];
            e1 = p32[4 * i + 2];
        }
        pq[k] = make_int2(e0 >> 1, e1 >> 1);
    }

    if (tid == 0) {
        mbar_init(mbar[0], 1);
        mbar_init(mbar[1], 1);
        s_next = grab_row();
    }
    __syncthreads();

    int r_cur = s_next;
    if (r_cur >= BATCH) return;   // immediate terminator (rare)

    // Prologue: start load of first row into in[0]; grab following row.
    if (tid == 0) {
        mbar_expect_tx(mbar[0], ROW_BYTES);
        bulk_load_row(sbase + SM_IN0, z + (long long)r_cur * DATA_DIM, mbar[0], pol);
        s_next = grab_row();
    }
    __syncthreads();
    int r_next = s_next;

    int s = 0;
    uint32_t ph0 = 0, ph1 = 0;

    while (true) {
        // Prefetch next row into in[s^1]; free outbuf[s]; grab row after next.
        if (tid == 0) {
            if (r_next < BATCH) {
                mbar_expect_tx(mbar[s ^ 1], ROW_BYTES);
                bulk_load_row(sbase + (s ? SM_IN0 : SM_IN1),
                              z + (long long)r_next * DATA_DIM, mbar[s ^ 1], pol);
                s_next = grab_row();
            }
            bulk_store_wait_read1();   // store issued 2 rows ago drained from smem
        }
        __syncthreads();               // outbuf[s] free + s_next visible to all
        const int r_next2 = s_next;

        // Wait for current row's TMA load.
        if (s == 0) { mbar_wait(mbar[0], ph0); ph0 ^= 1; }
        else        { mbar_wait(mbar[1], ph1); ph1 ^= 1; }

        // Gather in[s] -> outbuf[s] (random LDS.64 x2, conflict-free STS.128).
        {
            const float2* __restrict__ b = inb[s];
            float4* __restrict__ o = outb[s];
            #pragma unroll
            for (int k = 0; k < 4; k++) {
                int2 p = pq[k];
                float2 a = b[p.x];
                float2 c = b[p.y];
                o[tid + k * TPB] = make_float4(a.x, a.y, c.x, c.y);
            }
        }
        __syncthreads();          // all STS done; all reads of in[s] done

        // Issue async bulk store of the gathered row.
        if (tid == 0) {
            fence_async();
            bulk_store_row(out + (long long)r_cur * DATA_DIM,
                           sbase + (s ? SM_OUT1 : SM_OUT0), pol);
        }

        if (r_next >= BATCH) break;
        r_cur = r_next;
        r_next = r_next2;
        s ^= 1;
    }

    // Drain outstanding stores before exit.
    if (tid == 0) bulk_store_wait0();
}

extern "C" void kernel_launch(void* const* d_in, const int* in_sizes, int n_in,
                              void* d_out, int out_size) {
    const float* z    = (const float*)d_in[0];
    const void*  perm = d_in[1];
    float*       out  = (float*)d_out;

    cudaFuncSetAttribute(permute_tma_kernel,
                         cudaFuncAttributeMaxDynamicSharedMemorySize, SMEM_SZ);
    permute_tma_kernel<<<NBLK, TPB, SMEM_SZ>>>(z, perm, out);
}

// round 14
// speedup vs baseline: 1.0112x; 1.0112x over previous
#include <cuda_runtime.h>
#include <stdint.h>

#define DATA_DIM  4096
#define PAIRS     (DATA_DIM / 2)     // 2048
#define QUADS     (DATA_DIM / 4)     // 1024 float4 per row
#define BATCH     16384
#define WORK      (BATCH / 2)        // 8192 two-row work items
#define NBLK      (148 * 3)          // persistent CTAs, 3/SM (64KB smem each)
#define TPB       256
#define MODM      ((unsigned long long)(WORK + NBLK))
#define ROW_END   0x7fffffff
#define CHUNK_BYTES (2 * DATA_DIM * 4)   // 32768: two consecutive rows

// Dynamic smem: 2 x 32KB input buffers + mbarriers.
#define SM_IN(i)   ((i) * 32768)
#define SM_MBAR    65536
#define SMEM_SZ    (65536 + 64)

// Work-stealing counter. Zero at module load; each launch consumes exactly
// WORK real grabs + NBLK terminator grabs (each CTA stops grabbing at its
// first terminator), so the counter advances by exactly MODM per launch and
// item = v % MODM stays valid across graph replays with no reset.
__device__ unsigned long long g_ctr;

__device__ __forceinline__ void mbar_init(uint32_t mbar, uint32_t cnt) {
    asm volatile("mbarrier.init.shared.b64 [%0], %1;" :: "r"(mbar), "r"(cnt) : "memory");
}
__device__ __forceinline__ void mbar_expect_tx(uint32_t mbar, uint32_t bytes) {
    asm volatile("mbarrier.arrive.expect_tx.shared.b64 _, [%0], %1;"
                 :: "r"(mbar), "r"(bytes) : "memory");
}
__device__ __forceinline__ void mbar_wait(uint32_t mbar, uint32_t parity) {
    uint32_t done;
    asm volatile(
        "{\n\t.reg .pred p;\n\t"
        "mbarrier.try_wait.parity.acquire.cta.shared::cta.b64 p, [%1], %2;\n\t"
        "selp.b32 %0, 1, 0, p;\n\t}"
        : "=r"(done) : "r"(mbar), "r"(parity) : "memory");
    if (!done) {
        asm volatile(
            "{\n\t.reg .pred P1;\n\t"
            "W_%=:\n\t"
            "mbarrier.try_wait.parity.acquire.cta.shared::cta.b64 P1, [%0], %1, 0x989680;\n\t"
            "@P1 bra.uni D_%=;\n\t"
            "bra.uni W_%=;\n\t"
            "D_%=:\n\t}"
            :: "r"(mbar), "r"(parity) : "memory");
    }
}
__device__ __forceinline__ void bulk_load_chunk(uint32_t sdst, const void* gsrc, uint32_t mbar) {
    asm volatile(
        "cp.async.bulk.shared::cta.global.mbarrier::complete_tx::bytes [%0], [%1], %2, [%3];"
        :: "r"(sdst), "l"(gsrc), "r"((uint32_t)CHUNK_BYTES), "r"(mbar) : "memory");
}
__device__ __forceinline__ void fence_async() {
    asm volatile("fence.proxy.async.shared::cta;" ::: "memory");
}

// Persistent CTAs, depth-2 TMA input ring of 32KB (two consecutive rows per
// transaction -> longer contiguous DRAM bursts), register gather, direct
// coalesced STG.128 output. Atomic work stealing on two-row work items.
__global__ void __launch_bounds__(TPB)
permute_tma2row_kernel(const float* __restrict__ z, const void* __restrict__ perm,
                       float* __restrict__ out) {
    extern __shared__ char smem[];
    __shared__ int s_item[2];   // work item assigned to each pipeline slot

    const int tid = threadIdx.x;
    const uint32_t sbase = (uint32_t)__cvta_generic_to_shared(smem);

    // ---- Pair-map -> registers. Quad q needs source pairs perm[4q]>>1 and
    // perm[4q+2]>>1 (identical for both rows of a chunk; row 1 adds a PAIRS
    // offset in smem and a QUADS offset in the output). dtype detect:
    // perm[1] is always odd => int32 word[1]!=0; int64 high word of
    // perm[0] == 0 (little-endian).
    const int* p32 = (const int*)perm;
    const bool is64 = (p32[1] == 0) && (p32[3] == 0) && (p32[5] == 0) && (p32[7] == 0);
    int2 pq[4];
    #pragma unroll
    for (int k = 0; k < 4; k++) {
        int q = tid + k * TPB;
        int e0, e1;
        if (is64) {
            e0 = (int)((const long long*)perm)[4 * q];
            e1 = (int)((const long long*)perm)[4 * q + 2];
        } else {
            e0 = p32[4 * q];
            e1 = p32[4 * q + 2];
        }
        pq[k] = make_int2(e0 >> 1, e1 >> 1);
    }

    // ---- Prologue: init mbarriers, steal + issue up to 2 chunk loads.
    bool stop = false;   // meaningful in tid0 only
    if (tid == 0) {
        mbar_init(sbase + SM_MBAR, 1);
        mbar_init(sbase + SM_MBAR + 8, 1);
        fence_async();
        #pragma unroll
        for (int d = 0; d < 2; d++) {
            int it = ROW_END;
            if (!stop) {
                int v = (int)(atomicAdd(&g_ctr, 1ULL) % MODM);
                if (v < WORK) it = v; else stop = true;
            }
            s_item[d] = it;
            if (it != ROW_END) {
                mbar_expect_tx(sbase + SM_MBAR + 8 * d, CHUNK_BYTES);
                bulk_load_chunk(sbase + SM_IN(d),
                                z + (long long)it * (2 * DATA_DIM),
                                sbase + SM_MBAR + 8 * d);
            }
        }
    }
    __syncthreads();

    uint32_t ph[2] = {0, 0};
    int iter = 0;

    while (true) {
        const int slot = iter & 1;
        const int item = s_item[slot];
        if (item == ROW_END) break;

        // Wait for this slot's TMA load, then gather straight to gmem.
        mbar_wait(sbase + SM_MBAR + 8 * slot, ph[slot]);
        ph[slot] ^= 1;

        {
            const float2* __restrict__ b = (const float2*)(smem + SM_IN(slot));
            float4* __restrict__ o = (float4*)(out + (long long)item * (2 * DATA_DIM));
            // Row 0 (pairs [0,PAIRS), quads [0,QUADS))
            #pragma unroll
            for (int k = 0; k < 4; k++) {
                int2 p = pq[k];
                float2 a = b[p.x];
                float2 c = b[p.y];
                o[tid + k * TPB] = make_float4(a.x, a.y, c.x, c.y);
            }
            // Row 1 (pairs [PAIRS,2*PAIRS), quads [QUADS,2*QUADS))
            #pragma unroll
            for (int k = 0; k < 4; k++) {
                int2 p = pq[k];
                float2 a = b[PAIRS + p.x];
                float2 c = b[PAIRS + p.y];
                o[QUADS + tid + k * TPB] = make_float4(a.x, a.y, c.x, c.y);
            }
        }
        __syncthreads();   // all reads of in[slot] done before refill

        if (tid == 0) {
            int it = ROW_END;
            if (!stop) {
                int v = (int)(atomicAdd(&g_ctr, 1ULL) % MODM);
                if (v < WORK) it = v; else stop = true;
            }
            s_item[slot] = it;
            if (it != ROW_END) {
                mbar_expect_tx(sbase + SM_MBAR + 8 * slot, CHUNK_BYTES);
                bulk_load_chunk(sbase + SM_IN(slot),
                                z + (long long)it * (2 * DATA_DIM),
                                sbase + SM_MBAR + 8 * slot);
            }
        }
        iter++;
        __syncthreads();   // s_item[slot] visible before next use of this slot
    }
}

extern "C" void kernel_launch(void* const* d_in, const int* in_sizes, int n_in,
                              void* d_out, int out_size) {
    const float* z    = (const float*)d_in[0];
    const void*  perm = d_in[1];
    float*       out  = (float*)d_out;

    cudaFuncSetAttribute(permute_tma2row_kernel,
                         cudaFuncAttributeMaxDynamicSharedMemorySize, SMEM_SZ);
    permute_tma2row_kernel<<<NBLK, TPB, SMEM_SZ>>>(z, perm, out);
}